// round 17
// baseline (speedup 1.0000x reference)
#include <cuda_runtime.h>
#include <cuda_fp16.h>
#include <cstdint>
#include <cstddef>

#define NNODES 50000
#define RREL 8
#define NEDGE 100000
#define DIN0 768
#define DH 256
#define NBLKS 9
#define NCOLS (NBLKS*DH)   // 2304
#define RN (RREL*NNODES)   // 400000
#define TOTE (RREL*NEDGE)  // 800000
#define LN_EPS 1e-5f

// ---------------- scratch ---------------------------------------------------
__device__ __half g_Y[(size_t)NNODES * NCOLS];           // 230.4 MB (fp16 Y)
__device__ __half g_A[(size_t)NNODES * DIN0];            // 76.8 MB
__device__ __half g_W[(size_t)NCOLS * DIN0];             // 3.5 MB (max)
__device__ int   g_cnt[RN];
__device__ int   g_cursor[RN];
__device__ int   g_rowstart[RN];
__device__ int   g_eoff[TOTE];      // src*NCOLS + (r+1)*256  (element index)
__device__ float g_ew[TOTE];        // nw[src] / deg(r, tgt)
__device__ int   g_partials[512];

// ---------------- CSR setup (key = node*8 + r : node-contiguous) ------------
__global__ void k_zero() {
    int i = blockIdx.x * blockDim.x + threadIdx.x;
    if (i < RN) { g_cnt[i] = 0; g_cursor[i] = 0; }
}
__global__ void k_count(const int* __restrict__ tgt) {
    int e = blockIdx.x * blockDim.x + threadIdx.x;
    if (e < TOTE) atomicAdd(&g_cnt[tgt[e] * RREL + e / NEDGE], 1);
}
__global__ void k_scan1() {
    __shared__ int sh[1024];
    int i = blockIdx.x * 1024 + threadIdx.x;
    int v = (i < RN) ? g_cnt[i] : 0;
    sh[threadIdx.x] = v;
    for (int off = 1; off < 1024; off <<= 1) {
        __syncthreads();
        int t = (threadIdx.x >= off) ? sh[threadIdx.x - off] : 0;
        __syncthreads();
        sh[threadIdx.x] += t;
    }
    __syncthreads();
    if (i < RN) g_rowstart[i] = sh[threadIdx.x] - v;
    if (threadIdx.x == 1023) g_partials[blockIdx.x] = sh[1023];
}
__global__ void k_scan2(int nb) {
    __shared__ int sh[512];
    int v = (threadIdx.x < nb) ? g_partials[threadIdx.x] : 0;
    sh[threadIdx.x] = v;
    for (int off = 1; off < 512; off <<= 1) {
        __syncthreads();
        int t = (threadIdx.x >= off) ? sh[threadIdx.x - off] : 0;
        __syncthreads();
        sh[threadIdx.x] += t;
    }
    __syncthreads();
    if (threadIdx.x < nb) g_partials[threadIdx.x] = sh[threadIdx.x] - v;
}
__global__ void k_scan3() {
    int i = blockIdx.x * 1024 + threadIdx.x;
    if (i < RN) g_rowstart[i] += g_partials[blockIdx.x];
}
__global__ void k_fill(const int* __restrict__ src, const int* __restrict__ tgt,
                       const float* __restrict__ nw) {
    int e = blockIdx.x * blockDim.x + threadIdx.x;
    if (e >= TOTE) return;
    int r   = e / NEDGE;
    int key = tgt[e] * RREL + r;
    int pos = atomicAdd(&g_cursor[key], 1);
    int idx = g_rowstart[key] + pos;
    int s   = src[e];
    g_eoff[idx] = s * NCOLS + (r + 1) * DH;
    g_ew[idx]   = nw[s] / (float)g_cnt[key];
}

// ---------------- operand conversion (single fp16) ---------------------------
template <int K>
__global__ void k_buildA(const float* __restrict__ in, __half* __restrict__ out) {
    int i = blockIdx.x * blockDim.x + threadIdx.x;
    if (i < NNODES * K) out[i] = __float2half_rn(in[i]);
}
template <int K>
__global__ void k_buildW(const float* __restrict__ Wself, const float* __restrict__ Wrel,
                         __half* __restrict__ out) {
    int i = blockIdx.x * blockDim.x + threadIdx.x;
    if (i >= NCOLS * K) return;
    int c = i / K, k = i % K;
    int z = c >> 8, j = c & 255;
    float v = (z == 0) ? Wself[k * DH + j]
                       : Wrel[((size_t)(z - 1) * K + k) * DH + j];
    out[i] = __float2half_rn(v);
}

// --- mma.sync GEMM: CTA 64x256, 4 warps (1Mx4N), warp tile 64x64, 2 CTA/SM --
// 4-stage cp.async pipeline; both k16 fragment sets loaded before the MMA block.
#define BK 32
#define ROWB 80
#define SA_BYTES (64 * ROWB)
#define SB_BYTES (256 * ROWB)
#define STG_BYTES (SA_BYTES + SB_BYTES)
#define NSTAGE 4
#define SMEM_TOTAL (NSTAGE * STG_BYTES)   // 102400

__device__ __forceinline__ uint32_t smem_u32(const void* p) {
    uint32_t a;
    asm("{ .reg .u64 t; cvta.to.shared.u64 t, %1; cvt.u32.u64 %0, t; }" : "=r"(a) : "l"(p));
    return a;
}
__device__ __forceinline__ void cp16(uint32_t s, const void* g, uint32_t sz) {
    asm volatile("cp.async.cg.shared.global [%0], [%1], 16, %2;" :: "r"(s), "l"(g), "r"(sz) : "memory");
}
__device__ __forceinline__ void ldsm4(uint32_t& r0, uint32_t& r1, uint32_t& r2, uint32_t& r3, uint32_t a) {
    asm volatile("ldmatrix.sync.aligned.m8n8.x4.shared.b16 {%0,%1,%2,%3}, [%4];"
                 : "=r"(r0), "=r"(r1), "=r"(r2), "=r"(r3) : "r"(a));
}
__device__ __forceinline__ void mma16816(float* d, const uint32_t* a, const uint32_t* b) {
    asm volatile(
        "mma.sync.aligned.m16n8k16.row.col.f32.f16.f16.f32 "
        "{%0,%1,%2,%3}, {%4,%5,%6,%7}, {%8,%9}, {%0,%1,%2,%3};"
        : "+f"(d[0]), "+f"(d[1]), "+f"(d[2]), "+f"(d[3])
        : "r"(a[0]), "r"(a[1]), "r"(a[2]), "r"(a[3]), "r"(b[0]), "r"(b[1]));
}

template <int KP>
__global__ __launch_bounds__(128, 2)
void k_gemm_mma(const __half* __restrict__ A,
                const __half* __restrict__ B,
                __half* __restrict__ Y) {
    extern __shared__ char smem[];
    const uint32_t sb = smem_u32(smem);
    const int tid  = threadIdx.x;
    const int wid  = tid >> 5;        // 0..3 (N warps)
    const int lane = tid & 31;
    const int wn   = wid;

    const int c0 = blockIdx.x * 256;
    const int m0 = blockIdx.y * 64;

    float acc[4][8][4];
#pragma unroll
    for (int i = 0; i < 4; i++)
#pragma unroll
        for (int j = 0; j < 8; j++)
#pragma unroll
            for (int q = 0; q < 4; q++) acc[i][j][q] = 0.f;

    auto load_stage = [&](int it, int st) {
        const int k0 = it * BK;
        const uint32_t sA = sb + st * STG_BYTES;
        const uint32_t sB = sA + SA_BYTES;
#pragma unroll
        for (int j = 0; j < 2; j++) {          // 256 A chunks, 2/thread
            int ch = tid + j * 128;
            int row = ch >> 2, c4 = ch & 3;
            int grow = m0 + row;
            uint32_t ok = (grow < NNODES) ? 16u : 0u;
            const __half* src = A + (size_t)min(grow, NNODES - 1) * KP + k0 + c4 * 8;
            cp16(sA + row * ROWB + c4 * 16, src, ok);
        }
#pragma unroll
        for (int j = 0; j < 8; j++) {          // 1024 B chunks, 8/thread
            int ch = tid + j * 128;
            int row = ch >> 2, c4 = ch & 3;
            const __half* src = B + (size_t)(c0 + row) * KP + k0 + c4 * 8;
            cp16(sB + row * ROWB + c4 * 16, src, 16u);
        }
        asm volatile("cp.async.commit_group;" ::: "memory");
    };

    constexpr int ITERS = KP / BK;
    load_stage(0, 0);
    load_stage(1, 1);
    load_stage(2, 2);

    const uint32_t aLane = (uint32_t)((lane & 15) * ROWB + (lane >> 4) * 16);
    const uint32_t bLane = (uint32_t)(((lane & 7) + ((lane >> 4) << 3)) * ROWB + (((lane >> 3) & 1) * 16));

    for (int it = 0; it < ITERS; it++) {
        if (it < ITERS - 2)
            asm volatile("cp.async.wait_group 2;" ::: "memory");
        else if (it == ITERS - 2)
            asm volatile("cp.async.wait_group 1;" ::: "memory");
        else
            asm volatile("cp.async.wait_group 0;" ::: "memory");
        __syncthreads();

        const int nxt = it + 3;
        if (nxt < ITERS) load_stage(nxt, nxt & (NSTAGE - 1));

        const int st = it & (NSTAGE - 1);
        const uint32_t sA = sb + st * STG_BYTES;                       // full 64-row M
        const uint32_t sB = sb + st * STG_BYTES + SA_BYTES + (uint32_t)(wn * 64 * ROWB);

        // load ALL fragments for both k16 halves first, then one 64-MMA block
        uint32_t af[2][4][4];
        uint32_t bf[2][8][2];
#pragma unroll
        for (int ks = 0; ks < 2; ks++) {
#pragma unroll
            for (int mt = 0; mt < 4; mt++)
                ldsm4(af[ks][mt][0], af[ks][mt][1], af[ks][mt][2], af[ks][mt][3],
                      sA + aLane + (uint32_t)(mt * 16 * ROWB + ks * 32));
#pragma unroll
            for (int p = 0; p < 4; p++) {
                uint32_t r0, r1, r2, r3;
                ldsm4(r0, r1, r2, r3, sB + bLane + (uint32_t)(p * 16 * ROWB + ks * 32));
                bf[ks][2 * p][0] = r0; bf[ks][2 * p][1] = r1;
                bf[ks][2 * p + 1][0] = r2; bf[ks][2 * p + 1][1] = r3;
            }
        }
#pragma unroll
        for (int ks = 0; ks < 2; ks++)
#pragma unroll
            for (int mt = 0; mt < 4; mt++)
#pragma unroll
                for (int nt = 0; nt < 8; nt++)
                    mma16816(acc[mt][nt], af[ks][mt], bf[ks][nt]);
    }

    // epilogue: fp16 stores
    const int rbase = m0 + (lane >> 2);
    const int cbase = c0 + wn * 64 + ((lane & 3) << 1);
#pragma unroll
    for (int mt = 0; mt < 4; mt++) {
#pragma unroll
        for (int half = 0; half < 2; half++) {
            int row = rbase + mt * 16 + half * 8;
            if (row < NNODES) {
                __half* yp = Y + (size_t)row * NCOLS + cbase;
#pragma unroll
                for (int nt = 0; nt < 8; nt++) {
                    __half2 hv = __floats2half2_rn(acc[mt][nt][half * 2],
                                                   acc[mt][nt][half * 2 + 1]);
                    *(__half2*)(yp + nt * 8) = hv;
                }
            }
        }
    }
}

// --- fused aggregate (fp16 gather, MLP-8) + ReLU + LN (warp/node) -----------
__device__ __forceinline__ void acc_row8(const uint4 rv, float ww,
                                         float4& a0, float4& a1) {
    const __half2* h = (const __half2*)&rv;
    float2 f0 = __half22float2(h[0]);
    float2 f1 = __half22float2(h[1]);
    float2 f2 = __half22float2(h[2]);
    float2 f3 = __half22float2(h[3]);
    a0.x = fmaf(f0.x, ww, a0.x); a0.y = fmaf(f0.y, ww, a0.y);
    a0.z = fmaf(f1.x, ww, a0.z); a0.w = fmaf(f1.y, ww, a0.w);
    a1.x = fmaf(f2.x, ww, a1.x); a1.y = fmaf(f2.y, ww, a1.y);
    a1.z = fmaf(f3.x, ww, a1.z); a1.w = fmaf(f3.y, ww, a1.w);
}

template <bool TOHALF>
__global__ __launch_bounds__(256)
void k_agg_ln(const __half* __restrict__ Y,
              const float* __restrict__ bias,
              const float* __restrict__ lng,
              const float* __restrict__ lnb,
              float* __restrict__ outF,
              __half* __restrict__ outH) {
    const int n    = (blockIdx.x * 256 + threadIdx.x) >> 5;
    const int lane = threadIdx.x & 31;
    if (n >= NNODES) return;
    const int c = lane * 8;

    float4 a0, a1;
    {
        const uint4 rv = *(const uint4*)(Y + (size_t)n * NCOLS + c);
        const __half2* h = (const __half2*)&rv;
        float2 f0 = __half22float2(h[0]);
        float2 f1 = __half22float2(h[1]);
        float2 f2 = __half22float2(h[2]);
        float2 f3 = __half22float2(h[3]);
        float4 b0 = *(const float4*)(bias + c);
        float4 b1 = *(const float4*)(bias + c + 4);
        a0 = make_float4(f0.x + b0.x, f0.y + b0.y, f1.x + b0.z, f1.y + b0.w);
        a1 = make_float4(f2.x + b1.x, f2.y + b1.y, f3.x + b1.z, f3.y + b1.w);
    }

    const int beg = g_rowstart[n * RREL];
    const int end = (n == NNODES - 1) ? TOTE : g_rowstart[(n + 1) * RREL];

    for (int base = beg; base < end; base += 32) {
        const int m = min(32, end - base);
        int   off = 0;
        float w   = 0.f;
        if (lane < m) {
            off = g_eoff[base + lane];
            w   = g_ew[base + lane];
        }
        for (int j = 0; j < m; j += 8) {
            int   oq[8];
            float wq[8];
#pragma unroll
            for (int q = 0; q < 8; q++) {
                oq[q] = __shfl_sync(0xffffffffu, off, j + q);
                wq[q] = __shfl_sync(0xffffffffu, w,   j + q);
            }
#pragma unroll
            for (int q = 0; q < 8; q++) {
                const uint4 rv = *(const uint4*)(Y + oq[q] + c);
                acc_row8(rv, wq[q], a0, a1);
            }
        }
    }

    float v[8];
    v[0] = fmaxf(a0.x, 0.f); v[1] = fmaxf(a0.y, 0.f);
    v[2] = fmaxf(a0.z, 0.f); v[3] = fmaxf(a0.w, 0.f);
    v[4] = fmaxf(a1.x, 0.f); v[5] = fmaxf(a1.y, 0.f);
    v[6] = fmaxf(a1.z, 0.f); v[7] = fmaxf(a1.w, 0.f);

    float ps = 0.f;
#pragma unroll
    for (int q = 0; q < 8; q++) ps += v[q];
#pragma unroll
    for (int off2 = 16; off2 > 0; off2 >>= 1) ps += __shfl_xor_sync(0xffffffffu, ps, off2);
    const float mu = ps * (1.0f / DH);

    float d[8], pv = 0.f;
#pragma unroll
    for (int q = 0; q < 8; q++) { d[q] = v[q] - mu; pv = fmaf(d[q], d[q], pv); }
#pragma unroll
    for (int off2 = 16; off2 > 0; off2 >>= 1) pv += __shfl_xor_sync(0xffffffffu, pv, off2);
    const float rs = rsqrtf(pv * (1.0f / DH) + LN_EPS);

    float4 g0 = *(const float4*)(lng + c);
    float4 g1 = *(const float4*)(lng + c + 4);
    float4 e0 = *(const float4*)(lnb + c);
    float4 e1 = *(const float4*)(lnb + c + 4);
    float o[8];
    o[0] = d[0] * rs * g0.x + e0.x; o[1] = d[1] * rs * g0.y + e0.y;
    o[2] = d[2] * rs * g0.z + e0.z; o[3] = d[3] * rs * g0.w + e0.w;
    o[4] = d[4] * rs * g1.x + e1.x; o[5] = d[5] * rs * g1.y + e1.y;
    o[6] = d[6] * rs * g1.z + e1.z; o[7] = d[7] * rs * g1.w + e1.w;

    if (!TOHALF) {
        float4 o0 = make_float4(o[0], o[1], o[2], o[3]);
        float4 o1 = make_float4(o[4], o[5], o[6], o[7]);
        *(float4*)(outF + (size_t)n * DH + c)     = o0;
        *(float4*)(outF + (size_t)n * DH + c + 4) = o1;
    } else {
        __half hb[8];
#pragma unroll
        for (int q = 0; q < 8; q++) hb[q] = __float2half_rn(o[q]);
        *(uint4*)(outH + (size_t)n * DH + c) = *(uint4*)hb;
    }
}

// ---------------- launch -----------------------------------------------------
extern "C" void kernel_launch(void* const* d_in, const int* in_sizes, int n_in,
                              void* d_out, int out_size) {
    const float* x      = (const float*)d_in[0];
    const float* nw     = (const float*)d_in[1];
    const int*   es     = (const int*)d_in[2];
    const int*   et     = (const int*)d_in[3];
    const float* Wrel0  = (const float*)d_in[4];
    const float* Wself0 = (const float*)d_in[5];
    const float* b0     = (const float*)d_in[6];
    const float* g0     = (const float*)d_in[7];
    const float* be0    = (const float*)d_in[8];
    const float* Wrel1  = (const float*)d_in[9];
    const float* Wself1 = (const float*)d_in[10];
    const float* b1     = (const float*)d_in[11];
    const float* g1     = (const float*)d_in[12];
    const float* be1    = (const float*)d_in[13];
    float* out = (float*)d_out;

    __half *Yp, *Ap, *Wp;
    cudaGetSymbolAddress((void**)&Yp, g_Y);
    cudaGetSymbolAddress((void**)&Ap, g_A);
    cudaGetSymbolAddress((void**)&Wp, g_W);

    cudaFuncSetAttribute(k_gemm_mma<DIN0>, cudaFuncAttributeMaxDynamicSharedMemorySize, SMEM_TOTAL);
    cudaFuncSetAttribute(k_gemm_mma<DH>,   cudaFuncAttributeMaxDynamicSharedMemorySize, SMEM_TOTAL);

    const int nb1024 = (RN + 1023) / 1024;
    dim3 gg(NBLKS, (NNODES + 63) / 64);

    k_buildW<DIN0><<<(NCOLS * DIN0 + 255) / 256, 256>>>(Wself0, Wrel0, Wp);        // 0
    k_buildA<DIN0><<<(NNODES * DIN0 + 255) / 256, 256>>>(x, Ap);                   // 1
    k_zero<<<(RN + 255) / 256, 256>>>();                                           // 2
    k_gemm_mma<DIN0><<<gg, 128, SMEM_TOTAL>>>(Ap, Wp, Yp);                         // 3 <- profiled
    k_count<<<(TOTE + 255) / 256, 256>>>(et);                                      // 4
    k_scan1<<<nb1024, 1024>>>();                                                   // 5
    k_scan2<<<1, 512>>>(nb1024);                                                   // 6
    k_scan3<<<nb1024, 1024>>>();                                                   // 7
    k_fill<<<(TOTE + 255) / 256, 256>>>(es, et, nw);                               // 8
    k_agg_ln<true><<<(NNODES * 32 + 255) / 256, 256>>>(Yp, b0, g0, be0, nullptr, Ap); // 9

    k_buildW<DH><<<(NCOLS * DH + 255) / 256, 256>>>(Wself1, Wrel1, Wp);            // 10
    k_gemm_mma<DH><<<gg, 128, SMEM_TOTAL>>>(Ap, Wp, Yp);                           // 11
    k_agg_ln<false><<<(NNODES * 32 + 255) / 256, 256>>>(Yp, b1, g1, be1, out, nullptr); // 12
}